// round 1
// baseline (speedup 1.0000x reference)
#include <cuda_runtime.h>
#include <cstdint>

#define N_POS 4096
#define N_NEG 4096
#define N_NEU 2048
#define DIM   512

// 8 warps per block -> 8 row-constraints per block
#define THREADS 256
#define ROW_BLOCKS ((N_POS + N_NEG) / (THREADS / 32))      // 1024
#define NEU_BLOCKS ((N_NEU + THREADS - 1) / THREADS)       // 8

// total = 0.5 * sum / (N_POS + N_NEG + N_NEU)
#define SCALE (0.5f / (float)(N_POS + N_NEG + N_NEU))

__global__ void dcl_init(float* out) { *out = 0.0f; }

__global__ __launch_bounds__(THREADS) void dcl_kernel(
    const float* __restrict__ emb,
    const int* __restrict__ pos_ids, const int* __restrict__ pos_dims,
    const int* __restrict__ neg_ids, const int* __restrict__ neg_dims,
    const int* __restrict__ neu_ids, const int* __restrict__ neu_dims,
    float* __restrict__ out)
{
    const int lane = threadIdx.x & 31;
    const int warp_in_blk = threadIdx.x >> 5;

    float local = 0.0f;

    if (blockIdx.x < ROW_BLOCKS) {
        // ---- pos/neg row constraints: one warp per constraint ----
        int w = blockIdx.x * (THREADS / 32) + warp_in_blk;   // 0..8191
        bool positive = (w < N_POS);
        int idx = positive ? w : (w - N_POS);
        int id  = positive ? pos_ids[idx]  : neg_ids[idx];
        int dim = positive ? pos_dims[idx] : neg_dims[idx];

        const float4* row = reinterpret_cast<const float4*>(emb + (size_t)id * DIM);

        float s = 0.0f;   // sum |v| over row
        float t = 0.0f;   // value at target dim (only one lane sets it)
        #pragma unroll
        for (int i = 0; i < 4; i++) {
            int e = lane + i * 32;        // float4 index 0..127
            float4 v = row[e];
            s += fabsf(v.x) + fabsf(v.y) + fabsf(v.z) + fabsf(v.w);
            int base = e * 4;
            if (dim >= base && dim < base + 4) {
                float a[4] = {v.x, v.y, v.z, v.w};
                t = a[dim - base];
            }
        }
        #pragma unroll
        for (int o = 16; o; o >>= 1) {
            s += __shfl_xor_sync(0xFFFFFFFFu, s, o);
            t += __shfl_xor_sync(0xFFFFFFFFu, t, o);   // all other lanes hold 0
        }

        if (lane == 0) {
            float at = fabsf(t);
            float sign_loss;
            if (positive)
                sign_loss = (t <= 0.0f) ? (at + 0.1f) : (-0.1f * t);
            else
                sign_loss = (t >= 0.0f) ? (at + 0.1f) : (-0.1f * at);
            float sparsity = 0.1f * (s - at) * (1.0f / (float)(DIM - 1));
            local = sign_loss + sparsity;
        }
    } else {
        // ---- neutral constraints: one element per thread ----
        int i = (blockIdx.x - ROW_BLOCKS) * THREADS + threadIdx.x;
        if (i < N_NEU) {
            int id  = neu_ids[i];
            int dim = neu_dims[i];
            local = 2.0f * fabsf(__ldg(emb + (size_t)id * DIM + dim));
        }
    }

    // ---- block reduce -> one atomic per block ----
    #pragma unroll
    for (int o = 16; o; o >>= 1)
        local += __shfl_xor_sync(0xFFFFFFFFu, local, o);

    __shared__ float sh[THREADS / 32];
    if (lane == 0) sh[warp_in_blk] = local;
    __syncthreads();

    if (warp_in_blk == 0) {
        float v = (lane < THREADS / 32) ? sh[lane] : 0.0f;
        #pragma unroll
        for (int o = 4; o; o >>= 1)
            v += __shfl_xor_sync(0xFFFFFFFFu, v, o);
        if (lane == 0)
            atomicAdd(out, v * SCALE);
    }
}

extern "C" void kernel_launch(void* const* d_in, const int* in_sizes, int n_in,
                              void* d_out, int out_size)
{
    const float* emb      = (const float*)d_in[0];
    const int*   pos_ids  = (const int*)d_in[1];
    const int*   pos_dims = (const int*)d_in[2];
    const int*   neg_ids  = (const int*)d_in[3];
    const int*   neg_dims = (const int*)d_in[4];
    const int*   neu_ids  = (const int*)d_in[5];
    const int*   neu_dims = (const int*)d_in[6];
    float* out = (float*)d_out;

    dcl_init<<<1, 1>>>(out);
    dcl_kernel<<<ROW_BLOCKS + NEU_BLOCKS, THREADS>>>(
        emb, pos_ids, pos_dims, neg_ids, neg_dims, neu_ids, neu_dims, out);
}

// round 2
// speedup vs baseline: 1.0037x; 1.0037x over previous
#include <cuda_runtime.h>
#include <cstdint>

#define N_POS 4096
#define N_NEG 4096
#define N_NEU 2048
#define N_ROW (N_POS + N_NEG)            // 8192
#define DIM   512

#define THREADS 256
#define WARPS_PER_BLK (THREADS / 32)     // 8
#define ROWS_PER_WARP 2
#define ROW_BLOCKS (N_ROW / (WARPS_PER_BLK * ROWS_PER_WARP))   // 512
#define NEU_BLOCKS ((N_NEU + THREADS - 1) / THREADS)           // 8
#define GRID (ROW_BLOCKS + NEU_BLOCKS)                          // 520

#define SCALE (0.5f / (float)(N_POS + N_NEG + N_NEU))

__device__ float    g_accum = 0.0f;
__device__ unsigned g_count = 0u;

__device__ __forceinline__ float pick(const float4& v, int off) {
    // off in [0,4)
    float a = (off & 2) ? v.z : v.x;
    float b = (off & 2) ? v.w : v.y;
    return (off & 1) ? b : a;
}

__global__ __launch_bounds__(THREADS) void dcl_kernel(
    const float* __restrict__ emb,
    const int* __restrict__ pos_ids, const int* __restrict__ pos_dims,
    const int* __restrict__ neg_ids, const int* __restrict__ neg_dims,
    const int* __restrict__ neu_ids, const int* __restrict__ neu_dims,
    float* __restrict__ out)
{
    const int lane = threadIdx.x & 31;
    const int warp = threadIdx.x >> 5;

    float local = 0.0f;

    if (blockIdx.x < ROW_BLOCKS) {
        // ---- pos/neg: 2 row-constraints per warp, all 8 loads front-batched ----
        int w  = blockIdx.x * WARPS_PER_BLK + warp;
        int c0 = w * ROWS_PER_WARP;
        int c1 = c0 + 1;

        bool p0 = (c0 < N_POS), p1 = (c1 < N_POS);
        int i0 = p0 ? c0 : c0 - N_POS;
        int i1 = p1 ? c1 : c1 - N_POS;
        int id0  = p0 ? __ldg(pos_ids + i0)  : __ldg(neg_ids + i0);
        int dim0 = p0 ? __ldg(pos_dims + i0) : __ldg(neg_dims + i0);
        int id1  = p1 ? __ldg(pos_ids + i1)  : __ldg(neg_ids + i1);
        int dim1 = p1 ? __ldg(pos_dims + i1) : __ldg(neg_dims + i1);

        const float4* r0 = reinterpret_cast<const float4*>(emb + (size_t)id0 * DIM);
        const float4* r1 = reinterpret_cast<const float4*>(emb + (size_t)id1 * DIM);

        // issue all 8 independent LDG.128 before any consumption
        float4 a0 = r0[lane +  0], a1 = r0[lane + 32], a2 = r0[lane + 64], a3 = r0[lane + 96];
        float4 b0 = r1[lane +  0], b1 = r1[lane + 32], b2 = r1[lane + 64], b3 = r1[lane + 96];

        float s0 = fabsf(a0.x)+fabsf(a0.y)+fabsf(a0.z)+fabsf(a0.w)
                 + fabsf(a1.x)+fabsf(a1.y)+fabsf(a1.z)+fabsf(a1.w)
                 + fabsf(a2.x)+fabsf(a2.y)+fabsf(a2.z)+fabsf(a2.w)
                 + fabsf(a3.x)+fabsf(a3.y)+fabsf(a3.z)+fabsf(a3.w);
        float s1 = fabsf(b0.x)+fabsf(b0.y)+fabsf(b0.z)+fabsf(b0.w)
                 + fabsf(b1.x)+fabsf(b1.y)+fabsf(b1.z)+fabsf(b1.w)
                 + fabsf(b2.x)+fabsf(b2.y)+fabsf(b2.z)+fabsf(b2.w)
                 + fabsf(b3.x)+fabsf(b3.y)+fabsf(b3.z)+fabsf(b3.w);

        // target-dim extraction: the owning lane contributes, others 0
        float t0 = 0.0f, t1 = 0.0f;
        {
            int e = dim0 >> 2;              // float4 index 0..127
            if ((e & 31) == lane) {
                float4 v = (e < 32) ? a0 : (e < 64) ? a1 : (e < 96) ? a2 : a3;
                t0 = pick(v, dim0 & 3);
            }
            e = dim1 >> 2;
            if ((e & 31) == lane) {
                float4 v = (e < 32) ? b0 : (e < 64) ? b1 : (e < 96) ? b2 : b3;
                t1 = pick(v, dim1 & 3);
            }
        }

        #pragma unroll
        for (int o = 16; o; o >>= 1) {
            s0 += __shfl_xor_sync(0xFFFFFFFFu, s0, o);
            s1 += __shfl_xor_sync(0xFFFFFFFFu, s1, o);
            t0 += __shfl_xor_sync(0xFFFFFFFFu, t0, o);
            t1 += __shfl_xor_sync(0xFFFFFFFFu, t1, o);
        }

        if (lane == 0) {
            float at0 = fabsf(t0);
            float sl0 = p0 ? ((t0 <= 0.0f) ? (at0 + 0.1f) : (-0.1f * t0))
                           : ((t0 >= 0.0f) ? (at0 + 0.1f) : (-0.1f * at0));
            float at1 = fabsf(t1);
            float sl1 = p1 ? ((t1 <= 0.0f) ? (at1 + 0.1f) : (-0.1f * t1))
                           : ((t1 >= 0.0f) ? (at1 + 0.1f) : (-0.1f * at1));
            const float inv = 0.1f / (float)(DIM - 1);
            local = sl0 + (s0 - at0) * inv + sl1 + (s1 - at1) * inv;
        }
    } else {
        // ---- neutral: one element per thread ----
        int i = (blockIdx.x - ROW_BLOCKS) * THREADS + threadIdx.x;
        if (i < N_NEU) {
            int id  = __ldg(neu_ids + i);
            int dim = __ldg(neu_dims + i);
            local = 2.0f * fabsf(__ldg(emb + (size_t)id * DIM + dim));
        }
    }

    // ---- block reduce ----
    #pragma unroll
    for (int o = 16; o; o >>= 1)
        local += __shfl_xor_sync(0xFFFFFFFFu, local, o);

    __shared__ float sh[WARPS_PER_BLK];
    if (lane == 0) sh[warp] = local;
    __syncthreads();

    __shared__ bool isLast;
    if (threadIdx.x == 0) {
        float v = sh[0];
        #pragma unroll
        for (int k = 1; k < WARPS_PER_BLK; k++) v += sh[k];
        atomicAdd(&g_accum, v);
        __threadfence();
        unsigned n = atomicAdd(&g_count, 1u);
        isLast = (n == (unsigned)(GRID - 1));
    }
    __syncthreads();

    // ---- last block finalizes: writes out, resets scratch for next replay ----
    if (threadIdx.x == 0 && isLast) {
        __threadfence();
        float total = atomicExch(&g_accum, 0.0f);
        atomicExch(&g_count, 0u);
        out[0] = total * SCALE;
    }
}

extern "C" void kernel_launch(void* const* d_in, const int* in_sizes, int n_in,
                              void* d_out, int out_size)
{
    const float* emb      = (const float*)d_in[0];
    const int*   pos_ids  = (const int*)d_in[1];
    const int*   pos_dims = (const int*)d_in[2];
    const int*   neg_ids  = (const int*)d_in[3];
    const int*   neg_dims = (const int*)d_in[4];
    const int*   neu_ids  = (const int*)d_in[5];
    const int*   neu_dims = (const int*)d_in[6];

    dcl_kernel<<<GRID, THREADS>>>(
        emb, pos_ids, pos_dims, neg_ids, neg_dims, neu_ids, neu_dims,
        (float*)d_out);
}